// round 1
// baseline (speedup 1.0000x reference)
#include <cuda_runtime.h>

#define NN 100000
#define EE 1600000
#define RR 3
#define FF 128
#define HH 64
#define OO 32
#define BB 50000

// ---------------- scratch (no allocations allowed) ----------------
__device__ float g_h1[NN * HH];      // conv1 linear output
__device__ float g_agg1[NN * HH];    // conv1 aggregation
__device__ float g_x1[NN * HH];      // conv1 combined (pre-BN)
__device__ float g_h2[NN * OO];      // conv2 linear output
__device__ float g_agg2[NN * OO];
__device__ float g_x2[NN * OO];      // conv2 combined (pre-BN)
__device__ float g_dinv[NN];         // degree -> rsqrt(deg)
__device__ float g_stats[2 * HH];    // per-channel sum / sumsq
__device__ float g_bn[2 * HH];       // folded BN affine: a, b  (y = a*x + b)

// ---------------- GEMM: Y[n,C] = act(X)[n,K] @ W[K,C] + b ----------------
// blockDim 256 = 64 nodes x 4 column-groups. W staged in shared.
// FUSE: apply y = relu(a*x + b) (folded batchnorm) to X elements on load.
template <int K, int C, bool FUSE>
__global__ __launch_bounds__(256) void gemm_kernel(
    const float* __restrict__ X, const float* __restrict__ Wg,
    const float* __restrict__ bg, const float* __restrict__ bnp,
    float* __restrict__ Y, int nrows)
{
    constexpr int CPG = C / 4;
    __shared__ float sW[K * C];
    __shared__ float sBN[2 * K];
    int tid = threadIdx.x;
    for (int i = tid; i < K * C / 4; i += 256)
        ((float4*)sW)[i] = ((const float4*)Wg)[i];
    if (FUSE) {
        for (int i = tid; i < 2 * K; i += 256) sBN[i] = __ldg(bnp + i);
    }
    __syncthreads();

    int cg = tid & 3;
    int nl = tid >> 2;
    int row = blockIdx.x * 64 + nl;
    if (row >= nrows) return;

    float acc[CPG];
#pragma unroll
    for (int j = 0; j < CPG; j++) acc[j] = __ldg(bg + cg * CPG + j);

    const float4* Xr = (const float4*)(X + (size_t)row * K);
#pragma unroll 4
    for (int k4 = 0; k4 < K / 4; k4++) {
        float4 xv = __ldg(Xr + k4);
        float xs[4] = {xv.x, xv.y, xv.z, xv.w};
#pragma unroll
        for (int cc = 0; cc < 4; cc++) {
            int k = k4 * 4 + cc;
            float x = xs[cc];
            if (FUSE) x = fmaxf(0.f, fmaf(x, sBN[k], sBN[K + k]));
            const float* wrow = sW + k * C + cg * CPG;
#pragma unroll
            for (int j = 0; j < CPG; j++) acc[j] = fmaf(x, wrow[j], acc[j]);
        }
    }

    float4* Yr = (float4*)(Y + (size_t)row * C + cg * CPG);
#pragma unroll
    for (int j4 = 0; j4 < CPG / 4; j4++)
        Yr[j4] = make_float4(acc[4 * j4], acc[4 * j4 + 1],
                             acc[4 * j4 + 2], acc[4 * j4 + 3]);
}

// ---------------- degree ----------------
__global__ void degree_kernel(const int* __restrict__ dst, float* __restrict__ deg, int nE)
{
    int e = blockIdx.x * blockDim.x + threadIdx.x;
    if (e < nE) atomicAdd(deg + __ldg(dst + e), 1.0f);
}

__global__ void dinv_kernel(float* __restrict__ deg)
{
    int i = blockIdx.x * blockDim.x + threadIdx.x;
    if (i < NN) deg[i] = rsqrtf(fmaxf(deg[i], 1.0f));
}

// ---------------- edge scatter: agg[dst] += h[src] * dinv[src]*dinv[dst] ----------------
// One thread per (edge, 4-channel group); float4 vector atomics.
template <int C>
__global__ __launch_bounds__(256) void scatter_kernel(
    const float* __restrict__ h, const int* __restrict__ src,
    const int* __restrict__ dst, const float* __restrict__ dinv,
    float* __restrict__ agg, int nE)
{
    constexpr int TPE = C / 4;
    int idx = blockIdx.x * blockDim.x + threadIdx.x;
    int e = idx / TPE;
    if (e >= nE) return;
    int g = idx - e * TPE;
    int s = __ldg(src + e);
    int d = __ldg(dst + e);
    float norm = __ldg(dinv + s) * __ldg(dinv + d);
    float4 v = __ldg((const float4*)(h + (size_t)s * C) + g);
    v.x *= norm; v.y *= norm; v.z *= norm; v.w *= norm;
    atomicAdd((float4*)(agg + (size_t)d * C) + g, v);
}

// ---------------- combine + BN statistics ----------------
// x = gamma*agg + (1-gamma)*h ; accumulate per-channel sum/sumsq into g_stats.
// stride is a multiple of C, so each thread's channel is fixed.
template <int C>
__global__ __launch_bounds__(256) void combine_stats(
    const float* __restrict__ h, const float* __restrict__ agg,
    const float* __restrict__ gammaArr, int r, float* __restrict__ x)
{
    float gamma = __ldg(gammaArr + r);
    float og = 1.0f - gamma;
    int total = NN * C;
    int stride = gridDim.x * blockDim.x;
    int i0 = blockIdx.x * blockDim.x + threadIdx.x;
    float s = 0.f, s2 = 0.f;
    for (int i = i0; i < total; i += stride) {
        float v = fmaf(gamma, agg[i], og * h[i]);
        x[i] = v;
        s += v;
        s2 += v * v;
    }
    __shared__ float sh[256], sh2[256];
    sh[threadIdx.x] = s; sh2[threadIdx.x] = s2;
    __syncthreads();
    if (threadIdx.x < C) {
        float a = 0.f, b = 0.f;
        for (int t = threadIdx.x; t < 256; t += C) { a += sh[t]; b += sh2[t]; }
        int c = (blockIdx.x * 256 + threadIdx.x) % C;
        atomicAdd(&g_stats[c], a);
        atomicAdd(&g_stats[C + c], b);
    }
}

// ---------------- fold BN into affine (a,b) ----------------
template <int C>
__global__ void finalize_bn(const float* __restrict__ scale, const float* __restrict__ bias)
{
    int c = threadIdx.x;
    float mean = g_stats[c] * (1.0f / NN);
    float var = g_stats[C + c] * (1.0f / NN) - mean * mean;
    float inv = rsqrtf(var + 1e-5f);
    float a = __ldg(scale + c) * inv;
    g_bn[c] = a;
    g_bn[C + c] = __ldg(bias + c) - mean * a;
}

// ---------------- gather batch nodes + BN2 + relu + log_softmax ----------------
__global__ __launch_bounds__(256) void out_kernel(
    const float* __restrict__ x2, const int* __restrict__ bnodes,
    float* __restrict__ out, int r)
{
    int idx = blockIdx.x * blockDim.x + threadIdx.x;
    int b = idx >> 5;
    int lane = idx & 31;
    if (b >= BB) return;
    int node = __ldg(bnodes + b);
    float v = x2[(size_t)node * OO + lane];
    v = fmaxf(0.f, fmaf(v, g_bn[lane], g_bn[OO + lane]));
    float m = v;
#pragma unroll
    for (int o = 16; o; o >>= 1) m = fmaxf(m, __shfl_xor_sync(0xffffffffu, m, o));
    float e = expf(v - m);
    float ssum = e;
#pragma unroll
    for (int o = 16; o; o >>= 1) ssum += __shfl_xor_sync(0xffffffffu, ssum, o);
    out[(size_t)b * (RR * OO) + r * OO + lane] = v - m - logf(ssum);
}

// ---------------- launcher ----------------
extern "C" void kernel_launch(void* const* d_in, const int* in_sizes, int n_in,
                              void* d_out, int out_size)
{
    const float* features    = (const float*)d_in[0];
    const int*   edge_index  = (const int*)d_in[1];
    const int*   batch_nodes = (const int*)d_in[2];
    const float* W1 = (const float*)d_in[3];
    const float* b1 = (const float*)d_in[4];
    const float* W2 = (const float*)d_in[5];
    const float* b2 = (const float*)d_in[6];
    const float* gamma1 = (const float*)d_in[7];
    const float* gamma2 = (const float*)d_in[8];
    const float* bn1s = (const float*)d_in[9];
    const float* bn1b = (const float*)d_in[10];
    const float* bn2s = (const float*)d_in[11];
    const float* bn2b = (const float*)d_in[12];
    float* out = (float*)d_out;

    void *p_h1, *p_agg1, *p_x1, *p_h2, *p_agg2, *p_x2, *p_dinv, *p_stats, *p_bn;
    cudaGetSymbolAddress(&p_h1, g_h1);
    cudaGetSymbolAddress(&p_agg1, g_agg1);
    cudaGetSymbolAddress(&p_x1, g_x1);
    cudaGetSymbolAddress(&p_h2, g_h2);
    cudaGetSymbolAddress(&p_agg2, g_agg2);
    cudaGetSymbolAddress(&p_x2, g_x2);
    cudaGetSymbolAddress(&p_dinv, g_dinv);
    cudaGetSymbolAddress(&p_stats, g_stats);
    cudaGetSymbolAddress(&p_bn, g_bn);

    for (int r = 0; r < RR; r++) {
        const int* src = edge_index + (size_t)r * 2 * EE;
        const int* dst = src + EE;

        cudaMemsetAsync(p_dinv, 0, NN * sizeof(float));
        cudaMemsetAsync(p_agg1, 0, (size_t)NN * HH * sizeof(float));
        cudaMemsetAsync(p_stats, 0, 2 * HH * sizeof(float));

        // conv1 linear
        gemm_kernel<FF, HH, false><<<(NN + 63) / 64, 256>>>(
            features, W1 + (size_t)r * FF * HH, b1 + r * HH, nullptr,
            (float*)p_h1, NN);

        // degrees -> dinv
        degree_kernel<<<(EE + 255) / 256, 256>>>(dst, (float*)p_dinv, EE);
        dinv_kernel<<<(NN + 255) / 256, 256>>>((float*)p_dinv);

        // conv1 aggregate
        scatter_kernel<HH><<<(EE * (HH / 4) + 255) / 256, 256>>>(
            (const float*)p_h1, src, dst, (const float*)p_dinv,
            (float*)p_agg1, EE);

        // combine + BN1 stats
        combine_stats<HH><<<2048, 256>>>(
            (const float*)p_h1, (const float*)p_agg1, gamma1, r, (float*)p_x1);
        finalize_bn<HH><<<1, HH>>>(bn1s + r * HH, bn1b + r * HH);

        cudaMemsetAsync(p_agg2, 0, (size_t)NN * OO * sizeof(float));

        // conv2 linear with fused BN1-apply + relu on input
        gemm_kernel<HH, OO, true><<<(NN + 63) / 64, 256>>>(
            (const float*)p_x1, W2 + (size_t)r * HH * OO, b2 + r * OO,
            (const float*)p_bn, (float*)p_h2, NN);

        cudaMemsetAsync(p_stats, 0, 2 * HH * sizeof(float));

        // conv2 aggregate (same edges, same dinv)
        scatter_kernel<OO><<<(EE * (OO / 4) + 255) / 256, 256>>>(
            (const float*)p_h2, src, dst, (const float*)p_dinv,
            (float*)p_agg2, EE);

        // combine + BN2 stats
        combine_stats<OO><<<2048, 256>>>(
            (const float*)p_h2, (const float*)p_agg2, gamma2, r, (float*)p_x2);
        finalize_bn<OO><<<1, OO>>>(bn2s + r * OO, bn2b + r * OO);

        // gather + BN2-apply + relu + log_softmax
        out_kernel<<<(BB * 32 + 255) / 256, 256>>>(
            (const float*)p_x2, batch_nodes, out, r);
    }
}

// round 2
// speedup vs baseline: 1.1024x; 1.1024x over previous
#include <cuda_runtime.h>

#define NN 100000
#define EE 1600000
#define RR 3
#define FF 128
#define HH 64
#define OO 32
#define BB 50000
#define SCAN_BLKS ((NN + 1023) / 1024)

// ---------------- scratch ----------------
__device__ float g_h1[NN * HH];
__device__ float g_x1[NN * HH];
__device__ float g_h2[NN * OO];
__device__ float g_x2[NN * OO];
__device__ int   g_deg[NN];
__device__ float g_dinv[NN];
__device__ int   g_rowstart[NN];
__device__ int   g_cursor[NN];
__device__ int   g_bsums[SCAN_BLKS];
__device__ int   g_csr_src[EE];
__device__ float g_csr_norm[EE];
__device__ float g_stats[2 * HH];
__device__ float g_bn[2 * HH];

// ---------------- GEMM: Y[n,C] = act(X)[n,K] @ W[K,C] + b ----------------
template <int K, int C, bool FUSE>
__global__ __launch_bounds__(256) void gemm_kernel(
    const float* __restrict__ X, const float* __restrict__ Wg,
    const float* __restrict__ bg, const float* __restrict__ bnp,
    float* __restrict__ Y, int nrows)
{
    constexpr int CPG = C / 4;
    __shared__ float sW[K * C];
    __shared__ float sBN[2 * K];
    int tid = threadIdx.x;
    for (int i = tid; i < K * C / 4; i += 256)
        ((float4*)sW)[i] = ((const float4*)Wg)[i];
    if (FUSE) {
        for (int i = tid; i < 2 * K; i += 256) sBN[i] = __ldg(bnp + i);
    }
    __syncthreads();

    int cg = tid & 3;
    int nl = tid >> 2;
    int row = blockIdx.x * 64 + nl;
    if (row >= nrows) return;

    float acc[CPG];
#pragma unroll
    for (int j = 0; j < CPG; j++) acc[j] = __ldg(bg + cg * CPG + j);

    const float4* Xr = (const float4*)(X + (size_t)row * K);
#pragma unroll 4
    for (int k4 = 0; k4 < K / 4; k4++) {
        float4 xv = __ldg(Xr + k4);
        float xs[4] = {xv.x, xv.y, xv.z, xv.w};
#pragma unroll
        for (int cc = 0; cc < 4; cc++) {
            int k = k4 * 4 + cc;
            float x = xs[cc];
            if (FUSE) x = fmaxf(0.f, fmaf(x, sBN[k], sBN[K + k]));
            const float* wrow = sW + k * C + cg * CPG;
#pragma unroll
            for (int j = 0; j < CPG; j++) acc[j] = fmaf(x, wrow[j], acc[j]);
        }
    }

    float4* Yr = (float4*)(Y + (size_t)row * C + cg * CPG);
#pragma unroll
    for (int j4 = 0; j4 < CPG / 4; j4++)
        Yr[j4] = make_float4(acc[4 * j4], acc[4 * j4 + 1],
                             acc[4 * j4 + 2], acc[4 * j4 + 3]);
}

// ---------------- CSR build ----------------
__global__ void degree_kernel(const int* __restrict__ dst, int* __restrict__ deg)
{
    int e = blockIdx.x * blockDim.x + threadIdx.x;
    if (e < EE) atomicAdd(deg + __ldg(dst + e), 1);
}

__global__ void dinv_kernel(const int* __restrict__ deg, float* __restrict__ dinv)
{
    int i = blockIdx.x * blockDim.x + threadIdx.x;
    if (i < NN) dinv[i] = rsqrtf(fmaxf((float)deg[i], 1.0f));
}

// exclusive scan stage 1: per-1024 block scan
__global__ __launch_bounds__(1024) void scan_block(
    const int* __restrict__ deg, int* __restrict__ out, int* __restrict__ bsums)
{
    __shared__ int sh[1024];
    int i = blockIdx.x * 1024 + threadIdx.x;
    int v = (i < NN) ? deg[i] : 0;
    sh[threadIdx.x] = v;
    __syncthreads();
#pragma unroll
    for (int off = 1; off < 1024; off <<= 1) {
        int t = (threadIdx.x >= off) ? sh[threadIdx.x - off] : 0;
        __syncthreads();
        sh[threadIdx.x] += t;
        __syncthreads();
    }
    if (i < NN) out[i] = sh[threadIdx.x] - v;  // exclusive
    if (threadIdx.x == 1023) bsums[blockIdx.x] = sh[1023];
}

__global__ void scan_sums(int* __restrict__ bsums)
{
    if (threadIdx.x == 0) {
        int acc = 0;
        for (int i = 0; i < SCAN_BLKS; i++) {
            int t = bsums[i]; bsums[i] = acc; acc += t;
        }
    }
}

__global__ __launch_bounds__(1024) void scan_add(
    int* __restrict__ out, const int* __restrict__ bsums, int* __restrict__ cursor)
{
    int i = blockIdx.x * 1024 + threadIdx.x;
    if (i < NN) {
        int v = out[i] + bsums[blockIdx.x];
        out[i] = v;
        cursor[i] = v;
    }
}

__global__ __launch_bounds__(256) void fill_csr(
    const int* __restrict__ src, const int* __restrict__ dst,
    const float* __restrict__ dinv, int* __restrict__ cursor,
    int* __restrict__ csr_src, float* __restrict__ csr_norm)
{
    int e = blockIdx.x * blockDim.x + threadIdx.x;
    if (e >= EE) return;
    int s = __ldg(src + e);
    int d = __ldg(dst + e);
    int pos = atomicAdd(cursor + d, 1);
    csr_src[pos] = s;
    csr_norm[pos] = __ldg(dinv + s) * __ldg(dinv + d);
}

// ---------------- fused gather + combine + BN stats ----------------
// C channels per node; GPN = C/4 lanes per node, each lane owns a float4 group.
template <int C>
__global__ __launch_bounds__(256) void gather_combine(
    const float* __restrict__ h, const int* __restrict__ csr_src,
    const float* __restrict__ csr_norm, const int* __restrict__ row_start,
    const int* __restrict__ deg, const float* __restrict__ gammaArr, int r,
    float* __restrict__ x, float* __restrict__ stats)
{
    constexpr int GPN = C / 4;
    constexpr int NPB = 256 / GPN;
    __shared__ float sstats[2 * C];
    int tid = threadIdx.x;
    for (int i = tid; i < 2 * C; i += 256) sstats[i] = 0.f;
    __syncthreads();

    int g = tid & (GPN - 1);
    int nl = tid / GPN;
    int node = blockIdx.x * NPB + nl;

    if (node < NN) {
        float gamma = __ldg(gammaArr + r);
        float og = 1.0f - gamma;
        int start = __ldg(row_start + node);
        int end = start + __ldg(deg + node);
        float4 acc = make_float4(0.f, 0.f, 0.f, 0.f);

        int e = start;
        for (; e + 4 <= end; e += 4) {
            int s0 = __ldg(csr_src + e);
            int s1 = __ldg(csr_src + e + 1);
            int s2 = __ldg(csr_src + e + 2);
            int s3 = __ldg(csr_src + e + 3);
            float n0 = __ldg(csr_norm + e);
            float n1 = __ldg(csr_norm + e + 1);
            float n2 = __ldg(csr_norm + e + 2);
            float n3 = __ldg(csr_norm + e + 3);
            float4 v0 = __ldg((const float4*)(h + (size_t)s0 * C) + g);
            float4 v1 = __ldg((const float4*)(h + (size_t)s1 * C) + g);
            float4 v2 = __ldg((const float4*)(h + (size_t)s2 * C) + g);
            float4 v3 = __ldg((const float4*)(h + (size_t)s3 * C) + g);
            acc.x = fmaf(n0, v0.x, acc.x); acc.y = fmaf(n0, v0.y, acc.y);
            acc.z = fmaf(n0, v0.z, acc.z); acc.w = fmaf(n0, v0.w, acc.w);
            acc.x = fmaf(n1, v1.x, acc.x); acc.y = fmaf(n1, v1.y, acc.y);
            acc.z = fmaf(n1, v1.z, acc.z); acc.w = fmaf(n1, v1.w, acc.w);
            acc.x = fmaf(n2, v2.x, acc.x); acc.y = fmaf(n2, v2.y, acc.y);
            acc.z = fmaf(n2, v2.z, acc.z); acc.w = fmaf(n2, v2.w, acc.w);
            acc.x = fmaf(n3, v3.x, acc.x); acc.y = fmaf(n3, v3.y, acc.y);
            acc.z = fmaf(n3, v3.z, acc.z); acc.w = fmaf(n3, v3.w, acc.w);
        }
        for (; e < end; e++) {
            int s = __ldg(csr_src + e);
            float n = __ldg(csr_norm + e);
            float4 v = __ldg((const float4*)(h + (size_t)s * C) + g);
            acc.x = fmaf(n, v.x, acc.x); acc.y = fmaf(n, v.y, acc.y);
            acc.z = fmaf(n, v.z, acc.z); acc.w = fmaf(n, v.w, acc.w);
        }

        float4 hv = __ldg((const float4*)(h + (size_t)node * C) + g);
        float4 xv;
        xv.x = fmaf(gamma, acc.x, og * hv.x);
        xv.y = fmaf(gamma, acc.y, og * hv.y);
        xv.z = fmaf(gamma, acc.z, og * hv.z);
        xv.w = fmaf(gamma, acc.w, og * hv.w);
        ((float4*)(x + (size_t)node * C))[g] = xv;

        int c0 = g * 4;
        atomicAdd(&sstats[c0 + 0], xv.x);
        atomicAdd(&sstats[c0 + 1], xv.y);
        atomicAdd(&sstats[c0 + 2], xv.z);
        atomicAdd(&sstats[c0 + 3], xv.w);
        atomicAdd(&sstats[C + c0 + 0], xv.x * xv.x);
        atomicAdd(&sstats[C + c0 + 1], xv.y * xv.y);
        atomicAdd(&sstats[C + c0 + 2], xv.z * xv.z);
        atomicAdd(&sstats[C + c0 + 3], xv.w * xv.w);
    }
    __syncthreads();
    for (int i = tid; i < 2 * C; i += 256) atomicAdd(&stats[i], sstats[i]);
}

// ---------------- fold BN into affine (a,b) ----------------
template <int C>
__global__ void finalize_bn(const float* __restrict__ scale, const float* __restrict__ bias)
{
    int c = threadIdx.x;
    float mean = g_stats[c] * (1.0f / NN);
    float var = g_stats[C + c] * (1.0f / NN) - mean * mean;
    float inv = rsqrtf(var + 1e-5f);
    float a = __ldg(scale + c) * inv;
    g_bn[c] = a;
    g_bn[C + c] = __ldg(bias + c) - mean * a;
}

// ---------------- gather batch nodes + BN2 + relu + log_softmax ----------------
__global__ __launch_bounds__(256) void out_kernel(
    const float* __restrict__ x2, const int* __restrict__ bnodes,
    float* __restrict__ out, int r)
{
    int idx = blockIdx.x * blockDim.x + threadIdx.x;
    int b = idx >> 5;
    int lane = idx & 31;
    if (b >= BB) return;
    int node = __ldg(bnodes + b);
    float v = x2[(size_t)node * OO + lane];
    v = fmaxf(0.f, fmaf(v, g_bn[lane], g_bn[OO + lane]));
    float m = v;
#pragma unroll
    for (int o = 16; o; o >>= 1) m = fmaxf(m, __shfl_xor_sync(0xffffffffu, m, o));
    float e = expf(v - m);
    float ssum = e;
#pragma unroll
    for (int o = 16; o; o >>= 1) ssum += __shfl_xor_sync(0xffffffffu, ssum, o);
    out[(size_t)b * (RR * OO) + r * OO + lane] = v - m - logf(ssum);
}

// ---------------- launcher ----------------
extern "C" void kernel_launch(void* const* d_in, const int* in_sizes, int n_in,
                              void* d_out, int out_size)
{
    const float* features    = (const float*)d_in[0];
    const int*   edge_index  = (const int*)d_in[1];
    const int*   batch_nodes = (const int*)d_in[2];
    const float* W1 = (const float*)d_in[3];
    const float* b1 = (const float*)d_in[4];
    const float* W2 = (const float*)d_in[5];
    const float* b2 = (const float*)d_in[6];
    const float* gamma1 = (const float*)d_in[7];
    const float* gamma2 = (const float*)d_in[8];
    const float* bn1s = (const float*)d_in[9];
    const float* bn1b = (const float*)d_in[10];
    const float* bn2s = (const float*)d_in[11];
    const float* bn2b = (const float*)d_in[12];
    float* out = (float*)d_out;

    void *p_h1, *p_x1, *p_h2, *p_x2, *p_deg, *p_dinv, *p_rows, *p_cur,
         *p_bs, *p_csrs, *p_csrn, *p_stats, *p_bn;
    cudaGetSymbolAddress(&p_h1, g_h1);
    cudaGetSymbolAddress(&p_x1, g_x1);
    cudaGetSymbolAddress(&p_h2, g_h2);
    cudaGetSymbolAddress(&p_x2, g_x2);
    cudaGetSymbolAddress(&p_deg, g_deg);
    cudaGetSymbolAddress(&p_dinv, g_dinv);
    cudaGetSymbolAddress(&p_rows, g_rowstart);
    cudaGetSymbolAddress(&p_cur, g_cursor);
    cudaGetSymbolAddress(&p_bs, g_bsums);
    cudaGetSymbolAddress(&p_csrs, g_csr_src);
    cudaGetSymbolAddress(&p_csrn, g_csr_norm);
    cudaGetSymbolAddress(&p_stats, g_stats);
    cudaGetSymbolAddress(&p_bn, g_bn);

    for (int r = 0; r < RR; r++) {
        const int* src = edge_index + (size_t)r * 2 * EE;
        const int* dst = src + EE;

        cudaMemsetAsync(p_deg, 0, NN * sizeof(int));
        cudaMemsetAsync(p_stats, 0, 2 * HH * sizeof(float));

        // conv1 linear (overlappable with CSR build in graph order; serial stream ok)
        gemm_kernel<FF, HH, false><<<(NN + 63) / 64, 256>>>(
            features, W1 + (size_t)r * FF * HH, b1 + r * HH, nullptr,
            (float*)p_h1, NN);

        // CSR build
        degree_kernel<<<(EE + 255) / 256, 256>>>(dst, (int*)p_deg);
        dinv_kernel<<<(NN + 255) / 256, 256>>>((const int*)p_deg, (float*)p_dinv);
        scan_block<<<SCAN_BLKS, 1024>>>((const int*)p_deg, (int*)p_rows, (int*)p_bs);
        scan_sums<<<1, 32>>>((int*)p_bs);
        scan_add<<<SCAN_BLKS, 1024>>>((int*)p_rows, (const int*)p_bs, (int*)p_cur);
        fill_csr<<<(EE + 255) / 256, 256>>>(src, dst, (const float*)p_dinv,
                                            (int*)p_cur, (int*)p_csrs, (float*)p_csrn);

        // conv1 aggregate + combine + BN1 stats (fused)
        gather_combine<HH><<<(NN * (HH / 4) + 255) / 256, 256>>>(
            (const float*)p_h1, (const int*)p_csrs, (const float*)p_csrn,
            (const int*)p_rows, (const int*)p_deg, gamma1, r,
            (float*)p_x1, (float*)p_stats);
        finalize_bn<HH><<<1, HH>>>(bn1s + r * HH, bn1b + r * HH);

        // conv2 linear with fused BN1-apply + relu on input
        gemm_kernel<HH, OO, true><<<(NN + 63) / 64, 256>>>(
            (const float*)p_x1, W2 + (size_t)r * HH * OO, b2 + r * OO,
            (const float*)p_bn, (float*)p_h2, NN);

        cudaMemsetAsync(p_stats, 0, 2 * HH * sizeof(float));

        // conv2 aggregate + combine + BN2 stats (fused)
        gather_combine<OO><<<(NN * (OO / 4) + 255) / 256, 256>>>(
            (const float*)p_h2, (const int*)p_csrs, (const float*)p_csrn,
            (const int*)p_rows, (const int*)p_deg, gamma2, r,
            (float*)p_x2, (float*)p_stats);
        finalize_bn<OO><<<1, OO>>>(bn2s + r * OO, bn2b + r * OO);

        // gather + BN2-apply + relu + log_softmax
        out_kernel<<<(BB * 32 + 255) / 256, 256>>>(
            (const float*)p_x2, batch_nodes, out, r);
    }
}